// round 12
// baseline (speedup 1.0000x reference)
#include <cuda_runtime.h>
#include <cstdint>

#define NMAX 100000
#define EMAX 1600000
#define DD 128

// Scratch (static device arrays; allocation is forbidden)
__device__ float g_side[(size_t)NMAX * DD];
__device__ float g_P[(size_t)NMAX * DD];
__device__ float g_ego[(size_t)NMAX * DD];
__device__ int g_deg[NMAX];
__device__ int g_off[NMAX];
__device__ int g_cur[NMAX];
__device__ int g_blk[512];
__device__ int g_eidx[EMAX];

__global__ __launch_bounds__(256) void copy_kernel(const float* __restrict__ src,
                                                   float* __restrict__ dst, int n4) {
    int i = blockIdx.x * blockDim.x + threadIdx.x;
    if (i < n4) ((float4*)dst)[i] = ((const float4*)src)[i];
}

// ------------------------- CSR build (once per capture, reused by layers)
__global__ __launch_bounds__(256) void zero_deg_kernel(int n) {
    int i = blockIdx.x * blockDim.x + threadIdx.x;
    if (i < n) g_deg[i] = 0;
}

__global__ __launch_bounds__(256) void hist_kernel(const int* __restrict__ dst, int E) {
    int i = blockIdx.x * blockDim.x + threadIdx.x;
    if (i < E) atomicAdd(&g_deg[__ldg(dst + i)], 1);
}

__global__ __launch_bounds__(256) void scan_part_kernel(int n) {
    __shared__ int sh[256];
    int i = blockIdx.x * 256 + threadIdx.x;
    int v = (i < n) ? g_deg[i] : 0;
    sh[threadIdx.x] = v;
    __syncthreads();
    int incl = v;
#pragma unroll
    for (int o = 1; o < 256; o <<= 1) {
        int t = (threadIdx.x >= o) ? sh[threadIdx.x - o] : 0;
        __syncthreads();
        incl += t;
        sh[threadIdx.x] = incl;
        __syncthreads();
    }
    if (i < n) g_off[i] = incl - v;
    if (threadIdx.x == 255) g_blk[blockIdx.x] = incl;
}

__global__ __launch_bounds__(512) void scan_blk_kernel(int nb) {
    __shared__ int sh[512];
    int t = threadIdx.x;
    int v = (t < nb) ? g_blk[t] : 0;
    sh[t] = v;
    __syncthreads();
    int incl = v;
#pragma unroll
    for (int o = 1; o < 512; o <<= 1) {
        int x = (t >= o) ? sh[t - o] : 0;
        __syncthreads();
        incl += x;
        sh[t] = incl;
        __syncthreads();
    }
    if (t < nb) g_blk[t] = incl - v;
}

__global__ __launch_bounds__(256) void scan_add_kernel(int n) {
    int i = blockIdx.x * 256 + threadIdx.x;
    if (i < n) {
        int o = g_off[i] + g_blk[blockIdx.x];
        g_off[i] = o;
        g_cur[i] = o;
    }
}

__global__ __launch_bounds__(256) void scatter_kernel(const int* __restrict__ dst, int E) {
    int i = blockIdx.x * blockDim.x + threadIdx.x;
    if (i < E) {
        int pos = atomicAdd(&g_cur[__ldg(dst + i)], 1);
        g_eidx[pos] = i;
    }
}

// ------------------------- CSR SpMM: one warp per dst row, register acc.
__global__ __launch_bounds__(256) void spmm_csr_kernel(const float* __restrict__ x,
                                                       const int* __restrict__ src,
                                                       const float* __restrict__ val,
                                                       int N) {
    int row = (blockIdx.x * blockDim.x + threadIdx.x) >> 5;
    int lane = threadIdx.x & 31;
    if (row >= N) return;
    int off = g_off[row];
    int deg = g_deg[row];
    float4 acc = make_float4(0.f, 0.f, 0.f, 0.f);
    for (int j0 = 0; j0 < deg; j0 += 32) {
        int myj = j0 + lane;
        int e = (myj < deg) ? __ldg(g_eidx + off + myj) : 0;
        int s = __ldg(src + e);
        float v = (myj < deg) ? __ldg(val + e) : 0.f;
        int cnt = min(32, deg - j0);
        int t = 0;
        for (; t + 1 < cnt; t += 2) {
            int s0 = __shfl_sync(0xffffffffu, s, t);
            int s1 = __shfl_sync(0xffffffffu, s, t + 1);
            float v0 = __shfl_sync(0xffffffffu, v, t);
            float v1 = __shfl_sync(0xffffffffu, v, t + 1);
            float4 m0 = ((const float4*)(x + (size_t)s0 * DD))[lane];
            float4 m1 = ((const float4*)(x + (size_t)s1 * DD))[lane];
            acc.x += v0 * m0.x; acc.y += v0 * m0.y;
            acc.z += v0 * m0.z; acc.w += v0 * m0.w;
            acc.x += v1 * m1.x; acc.y += v1 * m1.y;
            acc.z += v1 * m1.z; acc.w += v1 * m1.w;
        }
        if (t < cnt) {
            int s0 = __shfl_sync(0xffffffffu, s, t);
            float v0 = __shfl_sync(0xffffffffu, v, t);
            float4 m0 = ((const float4*)(x + (size_t)s0 * DD))[lane];
            acc.x += v0 * m0.x; acc.y += v0 * m0.y;
            acc.z += v0 * m0.z; acc.w += v0 * m0.w;
        }
    }
    ((float4*)(g_side + (size_t)row * DD))[lane] = acc;
}

// ---------------- fused tf32 mma.sync GEMM ---------------------------------
// 64x128x128 tile per CTA, 256 threads, 8 warps (2m x 4n), warp tile 32x32.
// mode 1 (P pass):  A = ego*side; writes lrelu(P + bias) -> g_P
// mode 0 (S pass):  A = ego+side; e = lrelu(S + bias) + g_P; row-L2-norm;
//                   writes g_ego (un-normalized) and out_norm (normalized).
// SMEM: As 32KB (XOR swizzle row), Bs 64KB (XOR swizzle k), rowsum 256B.
#define AS_WORDS 8192
#define BS_WORDS 16384
#define GEMM_SMEM ((AS_WORDS + BS_WORDS + 64) * 4)

__device__ __forceinline__ uint32_t to_tf32(float f) {
    uint32_t u;
    asm("cvt.rna.tf32.f32 %0, %1;" : "=r"(u) : "f"(f));
    return u;
}
__device__ __forceinline__ float lrelu(float x) {
    return x > 0.f ? x : 0.01f * x;
}

__global__ __launch_bounds__(256, 2) void gemm_fused_kernel(const float* __restrict__ emb,
                                                            int use_g_ego,
                                                            const float* __restrict__ W,
                                                            const float* __restrict__ bias,
                                                            int mode,
                                                            float* __restrict__ out_norm,
                                                            int n_rows) {
    extern __shared__ uint32_t smem[];
    uint32_t* As = smem;                     // 8192 words (64 rows)
    uint32_t* Bs = smem + AS_WORDS;          // 16384 words (128 k-rows)
    float* rowsum = (float*)(smem + AS_WORDS + BS_WORDS);   // 64 floats

    const int tid = threadIdx.x;
    const int wid = tid >> 5;
    const int lane = tid & 31;
    const int row0 = blockIdx.x * 64;

    const float* __restrict__ ego = use_g_ego ? (const float*)g_ego : emb;

    if (tid < 64) rowsum[tid] = 0.f;

    // ---- fill (coalesced LDG.128 / swizzled STS.128)
    {
        const int col4 = tid & 31;
        const int rbase = tid >> 5;                 // 0..7 == row & 7 each pass
        const int a_sw = col4 ^ rbase;
        const int b_sw = col4 ^ ((rbase & 3) << 1);
#pragma unroll
        for (int j = 0; j < 8; j++) {               // A: 64 rows
            int row = j * 8 + rbase;
            int gr = row0 + row;
            float4 e = make_float4(0.f, 0.f, 0.f, 0.f), sd = e;
            if (gr < n_rows) {
                e = *(const float4*)(ego + (size_t)gr * DD + col4 * 4);
                sd = *(const float4*)(g_side + (size_t)gr * DD + col4 * 4);
            }
            float4 a;
            if (mode) { a.x = e.x * sd.x; a.y = e.y * sd.y; a.z = e.z * sd.z; a.w = e.w * sd.w; }
            else      { a.x = e.x + sd.x; a.y = e.y + sd.y; a.z = e.z + sd.z; a.w = e.w + sd.w; }
            ((uint4*)As)[row * 32 + a_sw] =
                make_uint4(to_tf32(a.x), to_tf32(a.y), to_tf32(a.z), to_tf32(a.w));
        }
#pragma unroll
        for (int j = 0; j < 16; j++) {              // B: 128 k-rows
            int k = j * 8 + rbase;
            float4 w = *(const float4*)(W + (size_t)k * DD + col4 * 4);
            ((uint4*)Bs)[k * 32 + b_sw] =
                make_uint4(to_tf32(w.x), to_tf32(w.y), to_tf32(w.z), to_tf32(w.w));
        }
    }
    __syncthreads();

    // ---- compute: warp tile 32(m) x 32(n); warps 2m x 4n
    const int warp_m = wid & 1;
    const int warp_n = wid >> 1;
    const int g = lane >> 2, tg = lane & 3;
    float acc[2][4][4];
#pragma unroll
    for (int mt = 0; mt < 2; mt++)
#pragma unroll
        for (int nt = 0; nt < 4; nt++)
#pragma unroll
            for (int q = 0; q < 4; q++) acc[mt][nt][q] = 0.f;

#pragma unroll 4
    for (int s = 0; s < 16; s++) {
        const int c4 = s * 2;
        uint32_t a[2][4];
#pragma unroll
        for (int mt = 0; mt < 2; mt++) {
            int r0 = warp_m * 32 + mt * 16 + g;      // r0 & 7 == g
            const uint32_t* lo = As + r0 * 128 + tg;
            const uint32_t* hi = As + (r0 + 8) * 128 + tg;
            a[mt][0] = lo[(c4 ^ g) * 4];
            a[mt][1] = hi[(c4 ^ g) * 4];
            a[mt][2] = lo[((c4 + 1) ^ g) * 4];
            a[mt][3] = hi[((c4 + 1) ^ g) * 4];
        }
        uint32_t b[4][2];
        const int k0 = s * 8 + tg;
        const int sw = tg << 1;
        const uint32_t* b0p = Bs + k0 * 128;
        const uint32_t* b1p = Bs + (k0 + 4) * 128;
#pragma unroll
        for (int nt = 0; nt < 4; nt++) {
            int n = warp_n * 32 + nt * 8 + g;
            int idx = ((n >> 2) ^ sw) * 4 + (n & 3);
            b[nt][0] = b0p[idx];
            b[nt][1] = b1p[idx];
        }
#pragma unroll
        for (int mt = 0; mt < 2; mt++)
#pragma unroll
            for (int nt = 0; nt < 4; nt++) {
                asm volatile(
                    "mma.sync.aligned.m16n8k8.row.col.f32.tf32.tf32.f32 "
                    "{%0,%1,%2,%3}, {%4,%5,%6,%7}, {%8,%9}, {%0,%1,%2,%3};"
                    : "+f"(acc[mt][nt][0]), "+f"(acc[mt][nt][1]),
                      "+f"(acc[mt][nt][2]), "+f"(acc[mt][nt][3])
                    : "r"(a[mt][0]), "r"(a[mt][1]), "r"(a[mt][2]), "r"(a[mt][3]),
                      "r"(b[nt][0]), "r"(b[nt][1]));
            }
    }

    // ---- epilogue
    if (mode) {
        // P pass: g_P = lrelu(P + bias)
#pragma unroll
        for (int mt = 0; mt < 2; mt++)
#pragma unroll
            for (int hi = 0; hi < 2; hi++) {
                int grow = row0 + warp_m * 32 + mt * 16 + hi * 8 + g;
                if (grow < n_rows) {
                    float* gp = g_P + (size_t)grow * DD + warp_n * 32 + tg * 2;
#pragma unroll
                    for (int nt = 0; nt < 4; nt++) {
                        float2 bv = *(const float2*)(bias + warp_n * 32 + nt * 8 + tg * 2);
                        float2 o;
                        o.x = lrelu(acc[mt][nt][hi * 2 + 0] + bv.x);
                        o.y = lrelu(acc[mt][nt][hi * 2 + 1] + bv.y);
                        *(float2*)(gp + nt * 8) = o;
                    }
                }
            }
    } else {
        // S pass: e = lrelu(S + bias) + g_P; norm; write g_ego + out_norm
#pragma unroll
        for (int mt = 0; mt < 2; mt++)
#pragma unroll
            for (int hi = 0; hi < 2; hi++) {
                int rl = warp_m * 32 + mt * 16 + hi * 8 + g;
                int grow = row0 + rl;
                float ps = 0.f;
                if (grow < n_rows) {
                    const float* gp = g_P + (size_t)grow * DD + warp_n * 32 + tg * 2;
#pragma unroll
                    for (int nt = 0; nt < 4; nt++) {
                        float2 bv = *(const float2*)(bias + warp_n * 32 + nt * 8 + tg * 2);
                        float2 pv = *(const float2*)(gp + nt * 8);
                        float e0 = lrelu(acc[mt][nt][hi * 2 + 0] + bv.x) + pv.x;
                        float e1 = lrelu(acc[mt][nt][hi * 2 + 1] + bv.y) + pv.y;
                        acc[mt][nt][hi * 2 + 0] = e0;
                        acc[mt][nt][hi * 2 + 1] = e1;
                        ps += e0 * e0 + e1 * e1;
                    }
                    atomicAdd(&rowsum[rl], ps);
                }
            }
        __syncthreads();
#pragma unroll
        for (int mt = 0; mt < 2; mt++)
#pragma unroll
            for (int hi = 0; hi < 2; hi++) {
                int rl = warp_m * 32 + mt * 16 + hi * 8 + g;
                int grow = row0 + rl;
                if (grow < n_rows) {
                    float inv = 1.f / fmaxf(sqrtf(rowsum[rl]), 1e-12f);
                    float* ep = g_ego + (size_t)grow * DD + warp_n * 32 + tg * 2;
                    float* op = out_norm + (size_t)grow * DD + warp_n * 32 + tg * 2;
#pragma unroll
                    for (int nt = 0; nt < 4; nt++) {
                        float e0 = acc[mt][nt][hi * 2 + 0];
                        float e1 = acc[mt][nt][hi * 2 + 1];
                        *(float2*)(ep + nt * 8) = make_float2(e0, e1);
                        *(float2*)(op + nt * 8) = make_float2(e0 * inv, e1 * inv);
                    }
                }
            }
    }
}

extern "C" void kernel_launch(void* const* d_in, const int* in_sizes, int n_in,
                              void* d_out, int out_size) {
    const float* emb    = (const float*)d_in[0];
    const int*   e_src  = (const int*)d_in[1];
    const int*   e_dst  = (const int*)d_in[2];
    const float* e_val  = (const float*)d_in[3];
    const float* W_sum  = (const float*)d_in[4];
    const float* b_sum  = (const float*)d_in[5];
    const float* W_prod = (const float*)d_in[6];
    const float* b_prod = (const float*)d_in[7];
    float* out = (float*)d_out;

    const int N = in_sizes[0] / DD;
    const int E = in_sizes[1];
    const int L = in_sizes[4] / (DD * DD);

    cudaFuncSetAttribute(gemm_fused_kernel,
                         cudaFuncAttributeMaxDynamicSharedMemorySize, GEMM_SMEM);

    const int n4 = N * (DD / 4);
    const int eb_blocks = (n4 + 255) / 256;
    const int nblocks = (N + 255) / 256;
    const int eblocks = (E + 255) / 256;

    copy_kernel<<<eb_blocks, 256>>>(emb, out, n4);

    // CSR build (reused by both layers)
    zero_deg_kernel<<<nblocks, 256>>>(N);
    hist_kernel<<<eblocks, 256>>>(e_dst, E);
    scan_part_kernel<<<nblocks, 256>>>(N);
    scan_blk_kernel<<<1, 512>>>(nblocks);
    scan_add_kernel<<<nblocks, 256>>>(N);
    scatter_kernel<<<eblocks, 256>>>(e_dst, E);

    const int spmm_blocks = (N + 7) / 8;
    const int gemm_bx = (N + 63) / 64;

    for (int i = 0; i < L; i++) {
        const float* x = out + (size_t)i * N * DD;   // normalized prev layer
        spmm_csr_kernel<<<spmm_blocks, 256>>>(x, e_src, e_val, N);
        gemm_fused_kernel<<<gemm_bx, 256, GEMM_SMEM>>>(
            emb, (i == 0) ? 0 : 1, W_prod + (size_t)i * DD * DD,
            b_prod + (size_t)i * DD, 1, nullptr, N);
        gemm_fused_kernel<<<gemm_bx, 256, GEMM_SMEM>>>(
            emb, (i == 0) ? 0 : 1, W_sum + (size_t)i * DD * DD,
            b_sum + (size_t)i * DD, 0, out + (size_t)(i + 1) * N * DD, N);
    }
}

// round 13
// speedup vs baseline: 1.0422x; 1.0422x over previous
#include <cuda_runtime.h>
#include <cstdint>

#define NMAX 100000
#define EMAX 1600000
#define DD 128

// Scratch (static device arrays; allocation is forbidden)
__device__ float g_side[(size_t)NMAX * DD];
__device__ float g_ego[(size_t)NMAX * DD];
__device__ int g_deg[NMAX];
__device__ int g_off[NMAX];
__device__ int g_cur[NMAX];
__device__ int g_blk[512];
__device__ int g_eidx[EMAX];

__global__ __launch_bounds__(256) void copy_kernel(const float* __restrict__ src,
                                                   float* __restrict__ dst, int n4) {
    int i = blockIdx.x * blockDim.x + threadIdx.x;
    if (i < n4) ((float4*)dst)[i] = ((const float4*)src)[i];
}

// ------------------------- CSR build (once per capture, reused by layers)
__global__ __launch_bounds__(256) void zero_deg_kernel(int n) {
    int i = blockIdx.x * blockDim.x + threadIdx.x;
    if (i < n) g_deg[i] = 0;
}

__global__ __launch_bounds__(256) void hist_kernel(const int* __restrict__ dst, int E) {
    int i = blockIdx.x * blockDim.x + threadIdx.x;
    if (i < E) atomicAdd(&g_deg[__ldg(dst + i)], 1);
}

__global__ __launch_bounds__(256) void scan_part_kernel(int n) {
    __shared__ int sh[256];
    int i = blockIdx.x * 256 + threadIdx.x;
    int v = (i < n) ? g_deg[i] : 0;
    sh[threadIdx.x] = v;
    __syncthreads();
    int incl = v;
#pragma unroll
    for (int o = 1; o < 256; o <<= 1) {
        int t = (threadIdx.x >= o) ? sh[threadIdx.x - o] : 0;
        __syncthreads();
        incl += t;
        sh[threadIdx.x] = incl;
        __syncthreads();
    }
    if (i < n) g_off[i] = incl - v;
    if (threadIdx.x == 255) g_blk[blockIdx.x] = incl;
}

__global__ __launch_bounds__(512) void scan_blk_kernel(int nb) {
    __shared__ int sh[512];
    int t = threadIdx.x;
    int v = (t < nb) ? g_blk[t] : 0;
    sh[t] = v;
    __syncthreads();
    int incl = v;
#pragma unroll
    for (int o = 1; o < 512; o <<= 1) {
        int x = (t >= o) ? sh[t - o] : 0;
        __syncthreads();
        incl += x;
        sh[t] = incl;
        __syncthreads();
    }
    if (t < nb) g_blk[t] = incl - v;
}

__global__ __launch_bounds__(256) void scan_add_kernel(int n) {
    int i = blockIdx.x * 256 + threadIdx.x;
    if (i < n) {
        int o = g_off[i] + g_blk[blockIdx.x];
        g_off[i] = o;
        g_cur[i] = o;
    }
}

__global__ __launch_bounds__(256) void scatter_kernel(const int* __restrict__ dst, int E) {
    int i = blockIdx.x * blockDim.x + threadIdx.x;
    if (i < E) {
        int pos = atomicAdd(&g_cur[__ldg(dst + i)], 1);
        g_eidx[pos] = i;
    }
}

// ------------------------- CSR SpMM: one warp per dst row, register acc.
__global__ __launch_bounds__(256) void spmm_csr_kernel(const float* __restrict__ x,
                                                       const int* __restrict__ src,
                                                       const float* __restrict__ val,
                                                       int N) {
    int row = (blockIdx.x * blockDim.x + threadIdx.x) >> 5;
    int lane = threadIdx.x & 31;
    if (row >= N) return;
    int off = g_off[row];
    int deg = g_deg[row];
    float4 acc = make_float4(0.f, 0.f, 0.f, 0.f);
    for (int j0 = 0; j0 < deg; j0 += 32) {
        int myj = j0 + lane;
        int e = (myj < deg) ? __ldg(g_eidx + off + myj) : 0;
        int s = __ldg(src + e);
        float v = (myj < deg) ? __ldg(val + e) : 0.f;
        int cnt = min(32, deg - j0);
        int t = 0;
        for (; t + 1 < cnt; t += 2) {
            int s0 = __shfl_sync(0xffffffffu, s, t);
            int s1 = __shfl_sync(0xffffffffu, s, t + 1);
            float v0 = __shfl_sync(0xffffffffu, v, t);
            float v1 = __shfl_sync(0xffffffffu, v, t + 1);
            float4 m0 = ((const float4*)(x + (size_t)s0 * DD))[lane];
            float4 m1 = ((const float4*)(x + (size_t)s1 * DD))[lane];
            acc.x += v0 * m0.x; acc.y += v0 * m0.y;
            acc.z += v0 * m0.z; acc.w += v0 * m0.w;
            acc.x += v1 * m1.x; acc.y += v1 * m1.y;
            acc.z += v1 * m1.z; acc.w += v1 * m1.w;
        }
        if (t < cnt) {
            int s0 = __shfl_sync(0xffffffffu, s, t);
            float v0 = __shfl_sync(0xffffffffu, v, t);
            float4 m0 = ((const float4*)(x + (size_t)s0 * DD))[lane];
            acc.x += v0 * m0.x; acc.y += v0 * m0.y;
            acc.z += v0 * m0.z; acc.w += v0 * m0.w;
        }
    }
    ((float4*)(g_side + (size_t)row * DD))[lane] = acc;
}

// ---------------- fully-fused dual tf32 GEMM layer -------------------------
// One kernel does the ENTIRE dense phase of a layer:
//   S = (ego+side) @ W_sum;  P = (ego*side) @ W_prod
//   e = lrelu(S + b_s) + lrelu(P + b_p);  row-L2-norm
//   writes g_ego (un-normalized) and out_norm (normalized).
// 64x128x128 tile/CTA, 256 threads, 8 warps (2m x 4n), warp tile 32x32,
// dual accumulators. ego/side read ONCE; no S/P intermediates in gmem.
#define AS_WORDS 8192                   // A:   64 rows x 128 (sum-input)
#define AP_WORDS 8192                   // A2:  64 rows x 128 (prod-input)
#define BS_WORDS 16384                  // each B: 128 x 128
#define GEMM_SMEM ((AS_WORDS + AP_WORDS + 2 * BS_WORDS + 64) * 4)   // ~196KB

__device__ __forceinline__ uint32_t to_tf32(float f) {
    uint32_t u;
    asm("cvt.rna.tf32.f32 %0, %1;" : "=r"(u) : "f"(f));
    return u;
}
__device__ __forceinline__ float lrelu(float x) {
    return x > 0.f ? x : 0.01f * x;
}

__global__ __launch_bounds__(256) void layer_fused_kernel(const float* __restrict__ emb,
                                                          int use_g_ego,
                                                          const float* __restrict__ W_sum,
                                                          const float* __restrict__ b_sum,
                                                          const float* __restrict__ W_prod,
                                                          const float* __restrict__ b_prod,
                                                          float* __restrict__ out_norm,
                                                          int n_rows) {
    extern __shared__ uint32_t smem[];
    uint32_t* AsS = smem;                            // sum input tile
    uint32_t* AsP = smem + AS_WORDS;                 // prod input tile
    uint32_t* BsS = smem + AS_WORDS + AP_WORDS;      // W_sum
    uint32_t* BsP = BsS + BS_WORDS;                  // W_prod
    float* rowsum = (float*)(BsP + BS_WORDS);        // 64 floats

    const int tid = threadIdx.x;
    const int wid = tid >> 5;
    const int lane = tid & 31;
    const int row0 = blockIdx.x * 64;

    const float* __restrict__ ego = use_g_ego ? (const float*)g_ego : emb;

    if (tid < 64) rowsum[tid] = 0.f;

    // ---- fill (coalesced LDG.128 / swizzled STS.128)
    {
        const int col4 = tid & 31;
        const int rbase = tid >> 5;                  // 0..7 == row & 7 each pass
        const int a_sw = col4 ^ rbase;
        const int b_sw = col4 ^ ((rbase & 3) << 1);
#pragma unroll
        for (int j = 0; j < 8; j++) {                // A: 64 rows, both variants
            int row = j * 8 + rbase;
            int gr = row0 + row;
            float4 e = make_float4(0.f, 0.f, 0.f, 0.f), sd = e;
            if (gr < n_rows) {
                e = *(const float4*)(ego + (size_t)gr * DD + col4 * 4);
                sd = *(const float4*)(g_side + (size_t)gr * DD + col4 * 4);
            }
            ((uint4*)AsS)[row * 32 + a_sw] =
                make_uint4(to_tf32(e.x + sd.x), to_tf32(e.y + sd.y),
                           to_tf32(e.z + sd.z), to_tf32(e.w + sd.w));
            ((uint4*)AsP)[row * 32 + a_sw] =
                make_uint4(to_tf32(e.x * sd.x), to_tf32(e.y * sd.y),
                           to_tf32(e.z * sd.z), to_tf32(e.w * sd.w));
        }
#pragma unroll
        for (int j = 0; j < 16; j++) {               // B: 128 k-rows, both mats
            int k = j * 8 + rbase;
            float4 w1 = *(const float4*)(W_sum + (size_t)k * DD + col4 * 4);
            ((uint4*)BsS)[k * 32 + b_sw] =
                make_uint4(to_tf32(w1.x), to_tf32(w1.y), to_tf32(w1.z), to_tf32(w1.w));
            float4 w2 = *(const float4*)(W_prod + (size_t)k * DD + col4 * 4);
            ((uint4*)BsP)[k * 32 + b_sw] =
                make_uint4(to_tf32(w2.x), to_tf32(w2.y), to_tf32(w2.z), to_tf32(w2.w));
        }
    }
    __syncthreads();

    // ---- compute: warp tile 32(m) x 32(n); warps 2m x 4n; dual accumulators
    const int warp_m = wid & 1;
    const int warp_n = wid >> 1;
    const int g = lane >> 2, tg = lane & 3;
    float accS[2][4][4], accP[2][4][4];
#pragma unroll
    for (int mt = 0; mt < 2; mt++)
#pragma unroll
        for (int nt = 0; nt < 4; nt++)
#pragma unroll
            for (int q = 0; q < 4; q++) { accS[mt][nt][q] = 0.f; accP[mt][nt][q] = 0.f; }

#pragma unroll 2
    for (int s = 0; s < 16; s++) {
        const int c4 = s * 2;
        uint32_t aS[2][4], aP[2][4];
#pragma unroll
        for (int mt = 0; mt < 2; mt++) {
            int r0 = warp_m * 32 + mt * 16 + g;      // r0 & 7 == g
            int i0 = (c4 ^ g) * 4, i1 = ((c4 + 1) ^ g) * 4;
            const uint32_t* loS = AsS + r0 * 128 + tg;
            const uint32_t* hiS = AsS + (r0 + 8) * 128 + tg;
            aS[mt][0] = loS[i0]; aS[mt][1] = hiS[i0];
            aS[mt][2] = loS[i1]; aS[mt][3] = hiS[i1];
            const uint32_t* loP = AsP + r0 * 128 + tg;
            const uint32_t* hiP = AsP + (r0 + 8) * 128 + tg;
            aP[mt][0] = loP[i0]; aP[mt][1] = hiP[i0];
            aP[mt][2] = loP[i1]; aP[mt][3] = hiP[i1];
        }
        const int k0 = s * 8 + tg;
        const int sw = tg << 1;
#pragma unroll
        for (int nt = 0; nt < 4; nt++) {
            int n = warp_n * 32 + nt * 8 + g;
            int idx = ((n >> 2) ^ sw) * 4 + (n & 3);
            uint32_t bS0 = BsS[k0 * 128 + idx];
            uint32_t bS1 = BsS[(k0 + 4) * 128 + idx];
            uint32_t bP0 = BsP[k0 * 128 + idx];
            uint32_t bP1 = BsP[(k0 + 4) * 128 + idx];
#pragma unroll
            for (int mt = 0; mt < 2; mt++) {
                asm volatile(
                    "mma.sync.aligned.m16n8k8.row.col.f32.tf32.tf32.f32 "
                    "{%0,%1,%2,%3}, {%4,%5,%6,%7}, {%8,%9}, {%0,%1,%2,%3};"
                    : "+f"(accS[mt][nt][0]), "+f"(accS[mt][nt][1]),
                      "+f"(accS[mt][nt][2]), "+f"(accS[mt][nt][3])
                    : "r"(aS[mt][0]), "r"(aS[mt][1]), "r"(aS[mt][2]), "r"(aS[mt][3]),
                      "r"(bS0), "r"(bS1));
                asm volatile(
                    "mma.sync.aligned.m16n8k8.row.col.f32.tf32.tf32.f32 "
                    "{%0,%1,%2,%3}, {%4,%5,%6,%7}, {%8,%9}, {%0,%1,%2,%3};"
                    : "+f"(accP[mt][nt][0]), "+f"(accP[mt][nt][1]),
                      "+f"(accP[mt][nt][2]), "+f"(accP[mt][nt][3])
                    : "r"(aP[mt][0]), "r"(aP[mt][1]), "r"(aP[mt][2]), "r"(aP[mt][3]),
                      "r"(bP0), "r"(bP1));
            }
        }
    }

    // ---- epilogue: e = lrelu(S+bs) + lrelu(P+bp); row norm; write ego + out
#pragma unroll
    for (int mt = 0; mt < 2; mt++)
#pragma unroll
        for (int hi = 0; hi < 2; hi++) {
            int rl = warp_m * 32 + mt * 16 + hi * 8 + g;
            int grow = row0 + rl;
            if (grow < n_rows) {
                float ps = 0.f;
#pragma unroll
                for (int nt = 0; nt < 4; nt++) {
                    float2 bvs = *(const float2*)(b_sum + warp_n * 32 + nt * 8 + tg * 2);
                    float2 bvp = *(const float2*)(b_prod + warp_n * 32 + nt * 8 + tg * 2);
                    float e0 = lrelu(accS[mt][nt][hi * 2 + 0] + bvs.x) +
                               lrelu(accP[mt][nt][hi * 2 + 0] + bvp.x);
                    float e1 = lrelu(accS[mt][nt][hi * 2 + 1] + bvs.y) +
                               lrelu(accP[mt][nt][hi * 2 + 1] + bvp.y);
                    accS[mt][nt][hi * 2 + 0] = e0;
                    accS[mt][nt][hi * 2 + 1] = e1;
                    ps += e0 * e0 + e1 * e1;
                }
                atomicAdd(&rowsum[rl], ps);
            }
        }
    __syncthreads();
#pragma unroll
    for (int mt = 0; mt < 2; mt++)
#pragma unroll
        for (int hi = 0; hi < 2; hi++) {
            int rl = warp_m * 32 + mt * 16 + hi * 8 + g;
            int grow = row0 + rl;
            if (grow < n_rows) {
                float inv = 1.f / fmaxf(sqrtf(rowsum[rl]), 1e-12f);
                float* ep = g_ego + (size_t)grow * DD + warp_n * 32 + tg * 2;
                float* op = out_norm + (size_t)grow * DD + warp_n * 32 + tg * 2;
#pragma unroll
                for (int nt = 0; nt < 4; nt++) {
                    float e0 = accS[mt][nt][hi * 2 + 0];
                    float e1 = accS[mt][nt][hi * 2 + 1];
                    *(float2*)(ep + nt * 8) = make_float2(e0, e1);
                    *(float2*)(op + nt * 8) = make_float2(e0 * inv, e1 * inv);
                }
            }
        }
}

extern "C" void kernel_launch(void* const* d_in, const int* in_sizes, int n_in,
                              void* d_out, int out_size) {
    const float* emb    = (const float*)d_in[0];
    const int*   e_src  = (const int*)d_in[1];
    const int*   e_dst  = (const int*)d_in[2];
    const float* e_val  = (const float*)d_in[3];
    const float* W_sum  = (const float*)d_in[4];
    const float* b_sum  = (const float*)d_in[5];
    const float* W_prod = (const float*)d_in[6];
    const float* b_prod = (const float*)d_in[7];
    float* out = (float*)d_out;

    const int N = in_sizes[0] / DD;
    const int E = in_sizes[1];
    const int L = in_sizes[4] / (DD * DD);

    cudaFuncSetAttribute(layer_fused_kernel,
                         cudaFuncAttributeMaxDynamicSharedMemorySize, GEMM_SMEM);

    const int n4 = N * (DD / 4);
    const int eb_blocks = (n4 + 255) / 256;
    const int nblocks = (N + 255) / 256;
    const int eblocks = (E + 255) / 256;

    copy_kernel<<<eb_blocks, 256>>>(emb, out, n4);

    // CSR build (reused by both layers)
    zero_deg_kernel<<<nblocks, 256>>>(N);
    hist_kernel<<<eblocks, 256>>>(e_dst, E);
    scan_part_kernel<<<nblocks, 256>>>(N);
    scan_blk_kernel<<<1, 512>>>(nblocks);
    scan_add_kernel<<<nblocks, 256>>>(N);
    scatter_kernel<<<eblocks, 256>>>(e_dst, E);

    const int spmm_blocks = (N + 7) / 8;
    const int gemm_bx = (N + 63) / 64;

    for (int i = 0; i < L; i++) {
        const float* x = out + (size_t)i * N * DD;   // normalized prev layer
        spmm_csr_kernel<<<spmm_blocks, 256>>>(x, e_src, e_val, N);
        layer_fused_kernel<<<gemm_bx, 256, GEMM_SMEM>>>(
            emb, (i == 0) ? 0 : 1,
            W_sum + (size_t)i * DD * DD, b_sum + (size_t)i * DD,
            W_prod + (size_t)i * DD * DD, b_prod + (size_t)i * DD,
            out + (size_t)(i + 1) * N * DD, N);
    }
}

// round 14
// speedup vs baseline: 1.1241x; 1.0786x over previous
#include <cuda_runtime.h>
#include <cstdint>

#define NMAX 100000
#define EMAX 1600000
#define DD 128

// Scratch (static device arrays; allocation is forbidden)
__device__ float g_side[(size_t)NMAX * DD];
__device__ float g_ego[(size_t)NMAX * DD];
__device__ int g_deg[NMAX];
__device__ int g_off[NMAX];
__device__ int g_cur[NMAX];
__device__ int g_blk[512];
__device__ int g_eidx[EMAX];

__global__ __launch_bounds__(256) void copy_kernel(const float* __restrict__ src,
                                                   float* __restrict__ dst, int n4) {
    int i = blockIdx.x * blockDim.x + threadIdx.x;
    if (i < n4) ((float4*)dst)[i] = ((const float4*)src)[i];
}

// ------------------------- CSR build (once per capture, reused by layers)
__global__ __launch_bounds__(256) void zero_deg_kernel(int n) {
    int i = blockIdx.x * blockDim.x + threadIdx.x;
    if (i < n) g_deg[i] = 0;
}

__global__ __launch_bounds__(256) void hist_kernel(const int* __restrict__ dst, int E) {
    int i = blockIdx.x * blockDim.x + threadIdx.x;
    if (i < E) atomicAdd(&g_deg[__ldg(dst + i)], 1);
}

__global__ __launch_bounds__(256) void scan_part_kernel(int n) {
    __shared__ int sh[256];
    int i = blockIdx.x * 256 + threadIdx.x;
    int v = (i < n) ? g_deg[i] : 0;
    sh[threadIdx.x] = v;
    __syncthreads();
    int incl = v;
#pragma unroll
    for (int o = 1; o < 256; o <<= 1) {
        int t = (threadIdx.x >= o) ? sh[threadIdx.x - o] : 0;
        __syncthreads();
        incl += t;
        sh[threadIdx.x] = incl;
        __syncthreads();
    }
    if (i < n) g_off[i] = incl - v;
    if (threadIdx.x == 255) g_blk[blockIdx.x] = incl;
}

__global__ __launch_bounds__(512) void scan_blk_kernel(int nb) {
    __shared__ int sh[512];
    int t = threadIdx.x;
    int v = (t < nb) ? g_blk[t] : 0;
    sh[t] = v;
    __syncthreads();
    int incl = v;
#pragma unroll
    for (int o = 1; o < 512; o <<= 1) {
        int x = (t >= o) ? sh[t - o] : 0;
        __syncthreads();
        incl += x;
        sh[t] = incl;
        __syncthreads();
    }
    if (t < nb) g_blk[t] = incl - v;
}

__global__ __launch_bounds__(256) void scan_add_kernel(int n) {
    int i = blockIdx.x * 256 + threadIdx.x;
    if (i < n) {
        int o = g_off[i] + g_blk[blockIdx.x];
        g_off[i] = o;
        g_cur[i] = o;
    }
}

__global__ __launch_bounds__(256) void scatter_kernel(const int* __restrict__ dst, int E) {
    int i = blockIdx.x * blockDim.x + threadIdx.x;
    if (i < E) {
        int pos = atomicAdd(&g_cur[__ldg(dst + i)], 1);
        g_eidx[pos] = i;
    }
}

// ------------------------- CSR SpMM: one warp per dst row, register acc.
__global__ __launch_bounds__(256) void spmm_csr_kernel(const float* __restrict__ x,
                                                       const int* __restrict__ src,
                                                       const float* __restrict__ val,
                                                       int N) {
    int row = (blockIdx.x * blockDim.x + threadIdx.x) >> 5;
    int lane = threadIdx.x & 31;
    if (row >= N) return;
    int off = g_off[row];
    int deg = g_deg[row];
    float4 acc = make_float4(0.f, 0.f, 0.f, 0.f);
    for (int j0 = 0; j0 < deg; j0 += 32) {
        int myj = j0 + lane;
        int e = (myj < deg) ? __ldg(g_eidx + off + myj) : 0;
        int s = __ldg(src + e);
        float v = (myj < deg) ? __ldg(val + e) : 0.f;
        int cnt = min(32, deg - j0);
        int t = 0;
        for (; t + 1 < cnt; t += 2) {
            int s0 = __shfl_sync(0xffffffffu, s, t);
            int s1 = __shfl_sync(0xffffffffu, s, t + 1);
            float v0 = __shfl_sync(0xffffffffu, v, t);
            float v1 = __shfl_sync(0xffffffffu, v, t + 1);
            float4 m0 = ((const float4*)(x + (size_t)s0 * DD))[lane];
            float4 m1 = ((const float4*)(x + (size_t)s1 * DD))[lane];
            acc.x += v0 * m0.x; acc.y += v0 * m0.y;
            acc.z += v0 * m0.z; acc.w += v0 * m0.w;
            acc.x += v1 * m1.x; acc.y += v1 * m1.y;
            acc.z += v1 * m1.z; acc.w += v1 * m1.w;
        }
        if (t < cnt) {
            int s0 = __shfl_sync(0xffffffffu, s, t);
            float v0 = __shfl_sync(0xffffffffu, v, t);
            float4 m0 = ((const float4*)(x + (size_t)s0 * DD))[lane];
            acc.x += v0 * m0.x; acc.y += v0 * m0.y;
            acc.z += v0 * m0.z; acc.w += v0 * m0.w;
        }
    }
    ((float4*)(g_side + (size_t)row * DD))[lane] = acc;
}

// ---------------- persistent fused dual tf32 GEMM layer --------------------
// 148 CTAs grid-stride over 64-row tiles; W_sum/W_prod staged in SMEM ONCE
// per CTA and reused for every tile. Per tile:
//   S = (ego+side) @ W_sum;  P = (ego*side) @ W_prod
//   e = lrelu(S+b_s) + lrelu(P+b_p);  row-L2-norm
//   writes g_ego (un-normalized) and out_norm (normalized).
#define AS_WORDS 8192                   // A sum-input: 64 rows x 128
#define AP_WORDS 8192                   // A prod-input
#define BS_WORDS 16384                  // each B: 128 x 128
#define GEMM_SMEM ((AS_WORDS + AP_WORDS + 2 * BS_WORDS + 64) * 4)   // ~196KB

__device__ __forceinline__ uint32_t to_tf32(float f) {
    uint32_t u;
    asm("cvt.rna.tf32.f32 %0, %1;" : "=r"(u) : "f"(f));
    return u;
}
__device__ __forceinline__ float lrelu(float x) {
    return x > 0.f ? x : 0.01f * x;
}

__global__ __launch_bounds__(256) void layer_fused_kernel(const float* __restrict__ emb,
                                                          int use_g_ego,
                                                          const float* __restrict__ W_sum,
                                                          const float* __restrict__ b_sum,
                                                          const float* __restrict__ W_prod,
                                                          const float* __restrict__ b_prod,
                                                          float* __restrict__ out_norm,
                                                          int n_rows, int n_tiles) {
    extern __shared__ uint32_t smem[];
    uint32_t* AsS = smem;                            // sum input tile
    uint32_t* AsP = smem + AS_WORDS;                 // prod input tile
    uint32_t* BsS = smem + AS_WORDS + AP_WORDS;      // W_sum
    uint32_t* BsP = BsS + BS_WORDS;                  // W_prod
    float* rowsum = (float*)(BsP + BS_WORDS);        // 64 floats

    const int tid = threadIdx.x;
    const int wid = tid >> 5;
    const int lane = tid & 31;

    const float* __restrict__ ego = use_g_ego ? (const float*)g_ego : emb;

    const int col4 = tid & 31;
    const int rbase = tid >> 5;                      // 0..7 == row & 7 each pass
    const int a_sw = col4 ^ rbase;
    const int b_sw = col4 ^ ((rbase & 3) << 1);

    // ---- stage both weight matrices once
#pragma unroll
    for (int j = 0; j < 16; j++) {
        int k = j * 8 + rbase;
        float4 w1 = *(const float4*)(W_sum + (size_t)k * DD + col4 * 4);
        ((uint4*)BsS)[k * 32 + b_sw] =
            make_uint4(to_tf32(w1.x), to_tf32(w1.y), to_tf32(w1.z), to_tf32(w1.w));
        float4 w2 = *(const float4*)(W_prod + (size_t)k * DD + col4 * 4);
        ((uint4*)BsP)[k * 32 + b_sw] =
            make_uint4(to_tf32(w2.x), to_tf32(w2.y), to_tf32(w2.z), to_tf32(w2.w));
    }

    const int warp_m = wid & 1;
    const int warp_n = wid >> 1;
    const int g = lane >> 2, tg = lane & 3;

    // bias values for this thread's columns (constant across tiles)
    float2 bvs[4], bvp[4];
#pragma unroll
    for (int nt = 0; nt < 4; nt++) {
        bvs[nt] = *(const float2*)(b_sum + warp_n * 32 + nt * 8 + tg * 2);
        bvp[nt] = *(const float2*)(b_prod + warp_n * 32 + nt * 8 + tg * 2);
    }

    for (int t = blockIdx.x; t < n_tiles; t += gridDim.x) {
        const int row0 = t * 64;
        if (tid < 64) rowsum[tid] = 0.f;

        // ---- A fill (coalesced LDG.128 / swizzled STS.128)
#pragma unroll
        for (int j = 0; j < 8; j++) {
            int row = j * 8 + rbase;
            int gr = row0 + row;
            float4 e = make_float4(0.f, 0.f, 0.f, 0.f), sd = e;
            if (gr < n_rows) {
                e = *(const float4*)(ego + (size_t)gr * DD + col4 * 4);
                sd = *(const float4*)(g_side + (size_t)gr * DD + col4 * 4);
            }
            ((uint4*)AsS)[row * 32 + a_sw] =
                make_uint4(to_tf32(e.x + sd.x), to_tf32(e.y + sd.y),
                           to_tf32(e.z + sd.z), to_tf32(e.w + sd.w));
            ((uint4*)AsP)[row * 32 + a_sw] =
                make_uint4(to_tf32(e.x * sd.x), to_tf32(e.y * sd.y),
                           to_tf32(e.z * sd.z), to_tf32(e.w * sd.w));
        }
        __syncthreads();

        // ---- compute: warp tile 32x32; dual accumulators
        float accS[2][4][4], accP[2][4][4];
#pragma unroll
        for (int mt = 0; mt < 2; mt++)
#pragma unroll
            for (int nt = 0; nt < 4; nt++)
#pragma unroll
                for (int q = 0; q < 4; q++) { accS[mt][nt][q] = 0.f; accP[mt][nt][q] = 0.f; }

#pragma unroll 2
        for (int s = 0; s < 16; s++) {
            const int c4 = s * 2;
            uint32_t aS[2][4], aP[2][4];
#pragma unroll
            for (int mt = 0; mt < 2; mt++) {
                int r0 = warp_m * 32 + mt * 16 + g;  // r0 & 7 == g
                int i0 = (c4 ^ g) * 4, i1 = ((c4 + 1) ^ g) * 4;
                const uint32_t* loS = AsS + r0 * 128 + tg;
                const uint32_t* hiS = AsS + (r0 + 8) * 128 + tg;
                aS[mt][0] = loS[i0]; aS[mt][1] = hiS[i0];
                aS[mt][2] = loS[i1]; aS[mt][3] = hiS[i1];
                const uint32_t* loP = AsP + r0 * 128 + tg;
                const uint32_t* hiP = AsP + (r0 + 8) * 128 + tg;
                aP[mt][0] = loP[i0]; aP[mt][1] = hiP[i0];
                aP[mt][2] = loP[i1]; aP[mt][3] = hiP[i1];
            }
            const int k0 = s * 8 + tg;
            const int sw = tg << 1;
#pragma unroll
            for (int nt = 0; nt < 4; nt++) {
                int n = warp_n * 32 + nt * 8 + g;
                int idx = ((n >> 2) ^ sw) * 4 + (n & 3);
                uint32_t bS0 = BsS[k0 * 128 + idx];
                uint32_t bS1 = BsS[(k0 + 4) * 128 + idx];
                uint32_t bP0 = BsP[k0 * 128 + idx];
                uint32_t bP1 = BsP[(k0 + 4) * 128 + idx];
#pragma unroll
                for (int mt = 0; mt < 2; mt++) {
                    asm volatile(
                        "mma.sync.aligned.m16n8k8.row.col.f32.tf32.tf32.f32 "
                        "{%0,%1,%2,%3}, {%4,%5,%6,%7}, {%8,%9}, {%0,%1,%2,%3};"
                        : "+f"(accS[mt][nt][0]), "+f"(accS[mt][nt][1]),
                          "+f"(accS[mt][nt][2]), "+f"(accS[mt][nt][3])
                        : "r"(aS[mt][0]), "r"(aS[mt][1]), "r"(aS[mt][2]), "r"(aS[mt][3]),
                          "r"(bS0), "r"(bS1));
                    asm volatile(
                        "mma.sync.aligned.m16n8k8.row.col.f32.tf32.tf32.f32 "
                        "{%0,%1,%2,%3}, {%4,%5,%6,%7}, {%8,%9}, {%0,%1,%2,%3};"
                        : "+f"(accP[mt][nt][0]), "+f"(accP[mt][nt][1]),
                          "+f"(accP[mt][nt][2]), "+f"(accP[mt][nt][3])
                        : "r"(aP[mt][0]), "r"(aP[mt][1]), "r"(aP[mt][2]), "r"(aP[mt][3]),
                          "r"(bP0), "r"(bP1));
                }
            }
        }

        // ---- epilogue: e = lrelu(S+bs) + lrelu(P+bp); row norm; write
#pragma unroll
        for (int mt = 0; mt < 2; mt++)
#pragma unroll
            for (int hi = 0; hi < 2; hi++) {
                int rl = warp_m * 32 + mt * 16 + hi * 8 + g;
                int grow = row0 + rl;
                if (grow < n_rows) {
                    float ps = 0.f;
#pragma unroll
                    for (int nt = 0; nt < 4; nt++) {
                        float e0 = lrelu(accS[mt][nt][hi * 2 + 0] + bvs[nt].x) +
                                   lrelu(accP[mt][nt][hi * 2 + 0] + bvp[nt].x);
                        float e1 = lrelu(accS[mt][nt][hi * 2 + 1] + bvs[nt].y) +
                                   lrelu(accP[mt][nt][hi * 2 + 1] + bvp[nt].y);
                        accS[mt][nt][hi * 2 + 0] = e0;
                        accS[mt][nt][hi * 2 + 1] = e1;
                        ps += e0 * e0 + e1 * e1;
                    }
                    atomicAdd(&rowsum[rl], ps);
                }
            }
        __syncthreads();
#pragma unroll
        for (int mt = 0; mt < 2; mt++)
#pragma unroll
            for (int hi = 0; hi < 2; hi++) {
                int rl = warp_m * 32 + mt * 16 + hi * 8 + g;
                int grow = row0 + rl;
                if (grow < n_rows) {
                    float inv = 1.f / fmaxf(sqrtf(rowsum[rl]), 1e-12f);
                    float* ep = g_ego + (size_t)grow * DD + warp_n * 32 + tg * 2;
                    float* op = out_norm + (size_t)grow * DD + warp_n * 32 + tg * 2;
#pragma unroll
                    for (int nt = 0; nt < 4; nt++) {
                        float e0 = accS[mt][nt][hi * 2 + 0];
                        float e1 = accS[mt][nt][hi * 2 + 1];
                        *(float2*)(ep + nt * 8) = make_float2(e0, e1);
                        *(float2*)(op + nt * 8) = make_float2(e0 * inv, e1 * inv);
                    }
                }
            }
        __syncthreads();   // protect rowsum/A tiles before next iteration
    }
}

extern "C" void kernel_launch(void* const* d_in, const int* in_sizes, int n_in,
                              void* d_out, int out_size) {
    const float* emb    = (const float*)d_in[0];
    const int*   e_src  = (const int*)d_in[1];
    const int*   e_dst  = (const int*)d_in[2];
    const float* e_val  = (const float*)d_in[3];
    const float* W_sum  = (const float*)d_in[4];
    const float* b_sum  = (const float*)d_in[5];
    const float* W_prod = (const float*)d_in[6];
    const float* b_prod = (const float*)d_in[7];
    float* out = (float*)d_out;

    const int N = in_sizes[0] / DD;
    const int E = in_sizes[1];
    const int L = in_sizes[4] / (DD * DD);

    cudaFuncSetAttribute(layer_fused_kernel,
                         cudaFuncAttributeMaxDynamicSharedMemorySize, GEMM_SMEM);

    const int n4 = N * (DD / 4);
    const int eb_blocks = (n4 + 255) / 256;
    const int nblocks = (N + 255) / 256;
    const int eblocks = (E + 255) / 256;

    copy_kernel<<<eb_blocks, 256>>>(emb, out, n4);

    // CSR build (reused by both layers)
    zero_deg_kernel<<<nblocks, 256>>>(N);
    hist_kernel<<<eblocks, 256>>>(e_dst, E);
    scan_part_kernel<<<nblocks, 256>>>(N);
    scan_blk_kernel<<<1, 512>>>(nblocks);
    scan_add_kernel<<<nblocks, 256>>>(N);
    scatter_kernel<<<eblocks, 256>>>(e_dst, E);

    const int spmm_blocks = (N + 7) / 8;
    const int n_tiles = (N + 63) / 64;
    const int pers_grid = 148;

    for (int i = 0; i < L; i++) {
        const float* x = out + (size_t)i * N * DD;   // normalized prev layer
        spmm_csr_kernel<<<spmm_blocks, 256>>>(x, e_src, e_val, N);
        layer_fused_kernel<<<pers_grid, 256, GEMM_SMEM>>>(
            emb, (i == 0) ? 0 : 1,
            W_sum + (size_t)i * DD * DD, b_sum + (size_t)i * DD,
            W_prod + (size_t)i * DD * DD, b_prod + (size_t)i * DD,
            out + (size_t)(i + 1) * N * DD, N, n_tiles);
    }
}